// round 11
// baseline (speedup 1.0000x reference)
#include <cuda_runtime.h>
#include <cuda_bf16.h>
#include <cuda_fp16.h>
#include <cstdint>

#define MAX_NODES 100000
#define MAX_EDGES 1600000
#define D 64
#define D2 (D / 2)
#define D4c 16              // k-chunks of 4

// ---------------------------------------------------------------------------
// Scratch (allocation-free rule -> device globals).
// ---------------------------------------------------------------------------
__device__ int g_deg[MAX_NODES];
__device__ int g_off[MAX_NODES];
__device__ int g_cursor[MAX_NODES];
__device__ int g_bsum[1024];
__device__ int g_elist[MAX_EDGES];
__device__ float2  g_h2[(size_t)MAX_NODES * D2];    // normalized neighbor means (fp32)
__device__ __half2 g_featH[(size_t)MAX_NODES * D2]; // fp16 copy of feat for gather

// ---------------------------------------------------------------------------
// K0: convert feat to fp16 (halves gather traffic; fp32 kept for GEMM/self)
// ---------------------------------------------------------------------------
__global__ void feat_to_half(const float2* __restrict__ feat2, int n) {
    int total = n * D2;
    int i = blockIdx.x * blockDim.x + threadIdx.x;
    if (i < total) {
        float2 v = feat2[i];
        g_featH[i] = __floats2half2_rn(v.x, v.y);
    }
}

// ---------------------------------------------------------------------------
// K1: zero degree counters
// ---------------------------------------------------------------------------
__global__ void zero_deg(int n) {
    int i = blockIdx.x * blockDim.x + threadIdx.x;
    if (i < n) g_deg[i] = 0;
}

// ---------------------------------------------------------------------------
// K2: count in-degree per dst (int32 indices)
// ---------------------------------------------------------------------------
__global__ void count_deg(const int* __restrict__ dst, int e) {
    int i = blockIdx.x * blockDim.x + threadIdx.x;
    if (i < e) atomicAdd(&g_deg[dst[i]], 1);
}

// ---------------------------------------------------------------------------
// K3a/b/c: exclusive scan of g_deg -> g_off  (1024 items per block)
// ---------------------------------------------------------------------------
__global__ __launch_bounds__(1024) void scan_blocks(int n) {
    __shared__ int s[1024];
    int tid = threadIdx.x;
    int i = blockIdx.x * 1024 + tid;
    int v = (i < n) ? g_deg[i] : 0;
    s[tid] = v;
    __syncthreads();
#pragma unroll
    for (int ofs = 1; ofs < 1024; ofs <<= 1) {
        int t = (tid >= ofs) ? s[tid - ofs] : 0;
        __syncthreads();
        s[tid] += t;
        __syncthreads();
    }
    if (i < n) g_off[i] = s[tid] - v;            // exclusive
    if (tid == 1023) g_bsum[blockIdx.x] = s[1023];
}

__global__ __launch_bounds__(1024) void scan_bsums(int nb) {
    __shared__ int s[1024];
    int tid = threadIdx.x;
    int v = (tid < nb) ? g_bsum[tid] : 0;
    s[tid] = v;
    __syncthreads();
#pragma unroll
    for (int ofs = 1; ofs < 1024; ofs <<= 1) {
        int t = (tid >= ofs) ? s[tid - ofs] : 0;
        __syncthreads();
        s[tid] += t;
        __syncthreads();
    }
    if (tid < nb) g_bsum[tid] = s[tid] - v;      // exclusive block offsets
}

__global__ void scan_add(int n) {
    int i = blockIdx.x * blockDim.x + threadIdx.x;
    if (i < n) {
        int o = g_off[i] + g_bsum[i >> 10];
        g_off[i] = o;
        g_cursor[i] = o;
    }
}

// ---------------------------------------------------------------------------
// K4: fill per-dst edge lists (src ids, grouped by dst)
// ---------------------------------------------------------------------------
__global__ void fill_elist(const int* __restrict__ src,
                           const int* __restrict__ dst, int e) {
    int i = blockIdx.x * blockDim.x + threadIdx.x;
    if (i < e) {
        int d = dst[i];
        int pos = atomicAdd(&g_cursor[d], 1);
        g_elist[pos] = src[i];
    }
}

// ---------------------------------------------------------------------------
// K5: gather (fp16 rows, fp32 accumulate). One warp per node; lane = half2
// chunk (32 x 4B = full 128B row, one coalesced sector-group per edge).
// ---------------------------------------------------------------------------
__global__ __launch_bounds__(256)
void gather_h(int n) {
    int warp = (blockIdx.x * 256 + threadIdx.x) >> 5;
    int lane = threadIdx.x & 31;
    if (warp >= n) return;
    int node  = warp;
    int start = g_off[node];
    int g     = g_deg[node];

    float2 acc = make_float2(0.f, 0.f);
    int k = 0;
    for (; k + 4 <= g; k += 4) {                 // unroll 4 for MLP
        int s0 = g_elist[start + k + 0];
        int s1 = g_elist[start + k + 1];
        int s2 = g_elist[start + k + 2];
        int s3 = g_elist[start + k + 3];
        float2 v0 = __half22float2(g_featH[(size_t)s0 * D2 + lane]);
        float2 v1 = __half22float2(g_featH[(size_t)s1 * D2 + lane]);
        float2 v2 = __half22float2(g_featH[(size_t)s2 * D2 + lane]);
        float2 v3 = __half22float2(g_featH[(size_t)s3 * D2 + lane]);
        acc.x += v0.x + v1.x + v2.x + v3.x;
        acc.y += v0.y + v1.y + v2.y + v3.y;
    }
    for (; k < g; k++) {
        int s0 = g_elist[start + k];
        float2 v0 = __half22float2(g_featH[(size_t)s0 * D2 + lane]);
        acc.x += v0.x; acc.y += v0.y;
    }
    float inv = 1.0f / (float)max(g, 1);
    acc.x *= inv; acc.y *= inv;
    g_h2[(size_t)node * D2 + lane] = acc;
}

// ---------------------------------------------------------------------------
// K6: register-blocked dual GEMM + bias + ReLU (unchanged from R10 WIN).
// 256 threads, 256 nodes/block (4 tiles of 64). Thread computes a 4-node x
// 4-col output tile. SMEM layouts k-chunk-major, conflict-free.
// ---------------------------------------------------------------------------
#define NT_BLOCK 256            // nodes per block
#define NT_TILE  64             // nodes per inner tile
#define SROW 65                 // padded row (float4) for sF/sH staging

#define OFF_WS 0                       // [16][64]
#define OFF_WN (OFF_WS + D4c * 64)     // [16][64]
#define OFF_SF (OFF_WN + D4c * 64)     // [16][SROW]
#define OFF_SH (OFF_SF + D4c * SROW)   // [16][SROW]
#define SMEM_F4_TOTAL (OFF_SH + D4c * SROW)

__global__ __launch_bounds__(256)
void sage_gemm(const float4* __restrict__ feat4,
               const float* __restrict__ W_self,
               const float* __restrict__ W_neigh,
               const float* __restrict__ bias,
               float* __restrict__ out,
               int n) {
    extern __shared__ float4 smem[];
    float4* wS = smem + OFF_WS;         // wS[kc][j] = Ws[4kc..4kc+3][j]
    float4* wN = smem + OFF_WN;
    float4* sF = smem + OFF_SF;         // sF[kc][node]
    float4* sH = smem + OFF_SH;

    int tid = threadIdx.x;
    int jt  = tid & 15;                 // cols jt, jt+16, jt+32, jt+48
    int nt  = tid >> 4;                 // nodes nt, nt+16, nt+32, nt+48 (in tile)

    // ---- stage weights once per block (k-chunk packed per column) ----
    {
        float* wsF = reinterpret_cast<float*>(wS);
        float* wnF = reinterpret_cast<float*>(wN);
#pragma unroll
        for (int q = 0; q < 16; q++) {
            int i = tid + 256 * q;      // i over 4096 = 64k x 64j
            int k = i >> 6, j = i & 63;
            int idx = ((k >> 2) * 64 + j) * 4 + (k & 3);
            wsF[idx] = W_self[i];
            wnF[idx] = W_neigh[i];
        }
    }

    float bj[4];
#pragma unroll
    for (int c = 0; c < 4; c++) bj[c] = bias[jt + 16 * c];

    const float4* h4 = reinterpret_cast<const float4*>(g_h2);
    int blockBase = blockIdx.x * NT_BLOCK;

    for (int t = 0; t < NT_BLOCK / NT_TILE; t++) {
        int base = blockBase + t * NT_TILE;
        __syncthreads();                 // protect smem from previous tile use

        // ---- stage 64 nodes of feat and h, transposed to [kc][node] ----
#pragma unroll
        for (int q = 0; q < 4; q++) {
            int i = tid + 256 * q;       // i over 1024 = 64 nodes x 16 kc
            int node = i >> 4, kc = i & 15;
            int gn = base + node;
            float4 fz = make_float4(0.f, 0.f, 0.f, 0.f);
            float4 fv = fz, hv = fz;
            if (gn < n) {
                fv = feat4[(size_t)gn * D4c + kc];
                hv = h4[(size_t)gn * D4c + kc];
            }
            sF[kc * SROW + node] = fv;
            sH[kc * SROW + node] = hv;
        }
        __syncthreads();

        // ---- compute 4x4 tile ----
        float acc[4][4];
#pragma unroll
        for (int r = 0; r < 4; r++)
#pragma unroll
            for (int c = 0; c < 4; c++) acc[r][c] = bj[c];

#pragma unroll
        for (int kc = 0; kc < D4c; kc++) {
            float4 wsv[4], wnv[4], fv[4], hv[4];
#pragma unroll
            for (int c = 0; c < 4; c++) {
                wsv[c] = wS[kc * 64 + jt + 16 * c];
                wnv[c] = wN[kc * 64 + jt + 16 * c];
            }
#pragma unroll
            for (int r = 0; r < 4; r++) {
                fv[r] = sF[kc * SROW + nt + 16 * r];
                hv[r] = sH[kc * SROW + nt + 16 * r];
            }
#pragma unroll
            for (int r = 0; r < 4; r++) {
#pragma unroll
                for (int c = 0; c < 4; c++) {
                    float a = acc[r][c];
                    a = fmaf(fv[r].x, wsv[c].x, a);
                    a = fmaf(fv[r].y, wsv[c].y, a);
                    a = fmaf(fv[r].z, wsv[c].z, a);
                    a = fmaf(fv[r].w, wsv[c].w, a);
                    a = fmaf(hv[r].x, wnv[c].x, a);
                    a = fmaf(hv[r].y, wnv[c].y, a);
                    a = fmaf(hv[r].z, wnv[c].z, a);
                    a = fmaf(hv[r].w, wnv[c].w, a);
                    acc[r][c] = a;
                }
            }
        }

        // ---- store ----
#pragma unroll
        for (int r = 0; r < 4; r++) {
            int gn = base + nt + 16 * r;
            if (gn < n) {
#pragma unroll
                for (int c = 0; c < 4; c++) {
                    out[(size_t)gn * D + jt + 16 * c] = fmaxf(acc[r][c], 0.f);
                }
            }
        }
    }
}

// ---------------------------------------------------------------------------
// Launch.  Inputs: feat[N*64] f32, src[E] i32, dst[E] i32,
//                  W_self[64*64] f32, W_neigh[64*64] f32, bias[64] f32
// ---------------------------------------------------------------------------
extern "C" void kernel_launch(void* const* d_in, const int* in_sizes, int n_in,
                              void* d_out, int out_size) {
    const float* feat    = (const float*)d_in[0];
    const int*   src     = (const int*)d_in[1];
    const int*   dst     = (const int*)d_in[2];
    const float* W_self  = (const float*)d_in[3];
    const float* W_neigh = (const float*)d_in[4];
    const float* bias    = (const float*)d_in[5];
    float*       out     = (float*)d_out;

    int n = in_sizes[0] / D;
    int e = in_sizes[1];

    int nb256  = (n + 255) / 256;
    int eb256  = (e + 255) / 256;
    int nScanB = (n + 1023) / 1024;
    int cvB    = (n * D2 + 255) / 256;

    feat_to_half<<<cvB, 256>>>(reinterpret_cast<const float2*>(feat), n);
    zero_deg<<<nb256, 256>>>(n);
    count_deg<<<eb256, 256>>>(dst, e);
    scan_blocks<<<nScanB, 1024>>>(n);
    scan_bsums<<<1, 1024>>>(nScanB);
    scan_add<<<nb256, 256>>>(n);
    fill_elist<<<eb256, 256>>>(src, dst, e);

    int gblocks = (n + 7) / 8;                    // one warp per node
    gather_h<<<gblocks, 256>>>(n);

    static int smem_set = 0;
    int smemBytes = SMEM_F4_TOTAL * sizeof(float4);   // ~66 KB
    if (!smem_set) {
        cudaFuncSetAttribute(sage_gemm, cudaFuncAttributeMaxDynamicSharedMemorySize,
                             smemBytes);
        smem_set = 1;
    }
    int gemmBlocks = (n + NT_BLOCK - 1) / NT_BLOCK;
    sage_gemm<<<gemmBlocks, 256, smemBytes>>>(
        reinterpret_cast<const float4*>(feat), W_self, W_neigh, bias, out, n);
}

// round 12
// speedup vs baseline: 1.0817x; 1.0817x over previous
#include <cuda_runtime.h>
#include <cuda_bf16.h>
#include <cstdint>

#define MAX_NODES 100000
#define MAX_EDGES 1600000
#define D 64
#define D2 (D / 2)
#define D4c 16              // k-chunks of 4

typedef unsigned long long u64t;

// ---------------------------------------------------------------------------
// Scratch (allocation-free rule -> device globals).
// ---------------------------------------------------------------------------
__device__ int g_deg[MAX_NODES];
__device__ int g_off[MAX_NODES];
__device__ int g_cursor[MAX_NODES];
__device__ int g_bsum[1024];
__device__ int g_elist[MAX_EDGES];
__device__ float2 g_h2[(size_t)MAX_NODES * D2];   // normalized neighbor means

// packed f32x2 FMA: acc.lo += a.lo*b.lo ; acc.hi += a.hi*b.hi
__device__ __forceinline__ void ffma2(u64t& acc, u64t a, u64t b) {
    asm("fma.rn.f32x2 %0, %1, %2, %0;" : "+l"(acc) : "l"(a), "l"(b));
}

// ---------------------------------------------------------------------------
// K1: zero degree counters
// ---------------------------------------------------------------------------
__global__ void zero_deg(int n) {
    int i = blockIdx.x * blockDim.x + threadIdx.x;
    if (i < n) g_deg[i] = 0;
}

// ---------------------------------------------------------------------------
// K2: count in-degree per dst (int32 indices)
// ---------------------------------------------------------------------------
__global__ void count_deg(const int* __restrict__ dst, int e) {
    int i = blockIdx.x * blockDim.x + threadIdx.x;
    if (i < e) atomicAdd(&g_deg[dst[i]], 1);
}

// ---------------------------------------------------------------------------
// K3a/b/c: exclusive scan of g_deg -> g_off  (1024 items per block)
// ---------------------------------------------------------------------------
__global__ __launch_bounds__(1024) void scan_blocks(int n) {
    __shared__ int s[1024];
    int tid = threadIdx.x;
    int i = blockIdx.x * 1024 + tid;
    int v = (i < n) ? g_deg[i] : 0;
    s[tid] = v;
    __syncthreads();
#pragma unroll
    for (int ofs = 1; ofs < 1024; ofs <<= 1) {
        int t = (tid >= ofs) ? s[tid - ofs] : 0;
        __syncthreads();
        s[tid] += t;
        __syncthreads();
    }
    if (i < n) g_off[i] = s[tid] - v;            // exclusive
    if (tid == 1023) g_bsum[blockIdx.x] = s[1023];
}

__global__ __launch_bounds__(1024) void scan_bsums(int nb) {
    __shared__ int s[1024];
    int tid = threadIdx.x;
    int v = (tid < nb) ? g_bsum[tid] : 0;
    s[tid] = v;
    __syncthreads();
#pragma unroll
    for (int ofs = 1; ofs < 1024; ofs <<= 1) {
        int t = (tid >= ofs) ? s[tid - ofs] : 0;
        __syncthreads();
        s[tid] += t;
        __syncthreads();
    }
    if (tid < nb) g_bsum[tid] = s[tid] - v;      // exclusive block offsets
}

__global__ void scan_add(int n) {
    int i = blockIdx.x * blockDim.x + threadIdx.x;
    if (i < n) {
        int o = g_off[i] + g_bsum[i >> 10];
        g_off[i] = o;
        g_cursor[i] = o;
    }
}

// ---------------------------------------------------------------------------
// K4: fill per-dst edge lists (src ids, grouped by dst)
// ---------------------------------------------------------------------------
__global__ void fill_elist(const int* __restrict__ src,
                           const int* __restrict__ dst, int e) {
    int i = blockIdx.x * blockDim.x + threadIdx.x;
    if (i < e) {
        int d = dst[i];
        int pos = atomicAdd(&g_cursor[d], 1);
        g_elist[pos] = src[i];
    }
}

// ---------------------------------------------------------------------------
// K5: gather (fp32). One warp per node; lane = float2 chunk.
// ---------------------------------------------------------------------------
__global__ __launch_bounds__(256)
void gather_h(const float2* __restrict__ feat2, int n) {
    int warp = (blockIdx.x * 256 + threadIdx.x) >> 5;
    int lane = threadIdx.x & 31;
    if (warp >= n) return;
    int node  = warp;
    int start = g_off[node];
    int g     = g_deg[node];

    float2 acc = make_float2(0.f, 0.f);
    int k = 0;
    for (; k + 4 <= g; k += 4) {                 // unroll 4 for MLP
        int s0 = g_elist[start + k + 0];
        int s1 = g_elist[start + k + 1];
        int s2 = g_elist[start + k + 2];
        int s3 = g_elist[start + k + 3];
        float2 v0 = feat2[(size_t)s0 * D2 + lane];
        float2 v1 = feat2[(size_t)s1 * D2 + lane];
        float2 v2 = feat2[(size_t)s2 * D2 + lane];
        float2 v3 = feat2[(size_t)s3 * D2 + lane];
        acc.x += v0.x + v1.x + v2.x + v3.x;
        acc.y += v0.y + v1.y + v2.y + v3.y;
    }
    for (; k < g; k++) {
        int s0 = g_elist[start + k];
        float2 v0 = feat2[(size_t)s0 * D2 + lane];
        acc.x += v0.x; acc.y += v0.y;
    }
    float inv = 1.0f / (float)max(g, 1);
    acc.x *= inv; acc.y *= inv;
    g_h2[(size_t)node * D2 + lane] = acc;
}

// ---------------------------------------------------------------------------
// K6: register-blocked dual GEMM + bias + ReLU, FFMA2 edition.
// Same tiling as R10 WIN (256 nodes/block, 4x4 tile per thread, k-chunk-major
// conflict-free SMEM). Inner product now uses fma.rn.f32x2: SMEM float4s are
// read as ulonglong2 so (even-k, odd-k) register pairs come straight from
// LDS.128 with zero packing instructions. Accumulator = (even-k partial,
// odd-k partial); one lo+hi add per output at the end.
// ---------------------------------------------------------------------------
#define NT_BLOCK 256            // nodes per block
#define NT_TILE  64             // nodes per inner tile
#define SROW 65                 // padded row (float4) for sF/sH staging

#define OFF_WS 0                       // [16][64]
#define OFF_WN (OFF_WS + D4c * 64)     // [16][64]
#define OFF_SF (OFF_WN + D4c * 64)     // [16][SROW]
#define OFF_SH (OFF_SF + D4c * SROW)   // [16][SROW]
#define SMEM_F4_TOTAL (OFF_SH + D4c * SROW)

__global__ __launch_bounds__(256)
void sage_gemm(const float4* __restrict__ feat4,
               const float* __restrict__ W_self,
               const float* __restrict__ W_neigh,
               const float* __restrict__ bias,
               float* __restrict__ out,
               int n) {
    extern __shared__ float4 smem[];
    float4* wS = smem + OFF_WS;         // wS[kc][j] = Ws[4kc..4kc+3][j]
    float4* wN = smem + OFF_WN;
    float4* sF = smem + OFF_SF;         // sF[kc][node]
    float4* sH = smem + OFF_SH;

    int tid = threadIdx.x;
    int jt  = tid & 15;                 // cols jt, jt+16, jt+32, jt+48
    int nt  = tid >> 4;                 // nodes nt, nt+16, nt+32, nt+48 (in tile)

    // ---- stage weights once per block (k-chunk packed per column) ----
    {
        float* wsF = reinterpret_cast<float*>(wS);
        float* wnF = reinterpret_cast<float*>(wN);
#pragma unroll
        for (int q = 0; q < 16; q++) {
            int i = tid + 256 * q;      // i over 4096 = 64k x 64j
            int k = i >> 6, j = i & 63;
            int idx = ((k >> 2) * 64 + j) * 4 + (k & 3);
            wsF[idx] = W_self[i];
            wnF[idx] = W_neigh[i];
        }
    }

    // acc pairs init: lo = bias, hi = 0
    u64t bj[4];
#pragma unroll
    for (int c = 0; c < 4; c++) bj[c] = (u64t)__float_as_uint(bias[jt + 16 * c]);

    const float4* h4 = reinterpret_cast<const float4*>(g_h2);
    int blockBase = blockIdx.x * NT_BLOCK;

    for (int t = 0; t < NT_BLOCK / NT_TILE; t++) {
        int base = blockBase + t * NT_TILE;
        __syncthreads();                 // protect smem from previous tile use

        // ---- stage 64 nodes of feat and h, transposed to [kc][node] ----
#pragma unroll
        for (int q = 0; q < 4; q++) {
            int i = tid + 256 * q;       // i over 1024 = 64 nodes x 16 kc
            int node = i >> 4, kc = i & 15;
            int gn = base + node;
            float4 fz = make_float4(0.f, 0.f, 0.f, 0.f);
            float4 fv = fz, hv = fz;
            if (gn < n) {
                fv = feat4[(size_t)gn * D4c + kc];
                hv = h4[(size_t)gn * D4c + kc];
            }
            sF[kc * SROW + node] = fv;
            sH[kc * SROW + node] = hv;
        }
        __syncthreads();

        // ---- compute 4x4 tile with f32x2 ----
        u64t acc[4][4];
#pragma unroll
        for (int r = 0; r < 4; r++)
#pragma unroll
            for (int c = 0; c < 4; c++) acc[r][c] = bj[c];

#pragma unroll
        for (int kc = 0; kc < D4c; kc++) {
            ulonglong2 wsv[4], wnv[4], fv[4], hv[4];
#pragma unroll
            for (int c = 0; c < 4; c++) {
                wsv[c] = *reinterpret_cast<const ulonglong2*>(&wS[kc * 64 + jt + 16 * c]);
                wnv[c] = *reinterpret_cast<const ulonglong2*>(&wN[kc * 64 + jt + 16 * c]);
            }
#pragma unroll
            for (int r = 0; r < 4; r++) {
                fv[r] = *reinterpret_cast<const ulonglong2*>(&sF[kc * SROW + nt + 16 * r]);
                hv[r] = *reinterpret_cast<const ulonglong2*>(&sH[kc * SROW + nt + 16 * r]);
            }
#pragma unroll
            for (int r = 0; r < 4; r++) {
#pragma unroll
                for (int c = 0; c < 4; c++) {
                    ffma2(acc[r][c], fv[r].x, wsv[c].x);   // k0,k1 (self)
                    ffma2(acc[r][c], fv[r].y, wsv[c].y);   // k2,k3 (self)
                    ffma2(acc[r][c], hv[r].x, wnv[c].x);   // k0,k1 (neigh)
                    ffma2(acc[r][c], hv[r].y, wnv[c].y);   // k2,k3 (neigh)
                }
            }
        }

        // ---- store: fold (even,odd) halves, bias already in lo ----
#pragma unroll
        for (int r = 0; r < 4; r++) {
            int gn = base + nt + 16 * r;
            if (gn < n) {
#pragma unroll
                for (int c = 0; c < 4; c++) {
                    u64t a = acc[r][c];
                    float v = __uint_as_float((unsigned)a) +
                              __uint_as_float((unsigned)(a >> 32));
                    out[(size_t)gn * D + jt + 16 * c] = fmaxf(v, 0.f);
                }
            }
        }
    }
}

// ---------------------------------------------------------------------------
// Launch.  Inputs: feat[N*64] f32, src[E] i32, dst[E] i32,
//                  W_self[64*64] f32, W_neigh[64*64] f32, bias[64] f32
// ---------------------------------------------------------------------------
extern "C" void kernel_launch(void* const* d_in, const int* in_sizes, int n_in,
                              void* d_out, int out_size) {
    const float* feat    = (const float*)d_in[0];
    const int*   src     = (const int*)d_in[1];
    const int*   dst     = (const int*)d_in[2];
    const float* W_self  = (const float*)d_in[3];
    const float* W_neigh = (const float*)d_in[4];
    const float* bias    = (const float*)d_in[5];
    float*       out     = (float*)d_out;

    int n = in_sizes[0] / D;
    int e = in_sizes[1];

    int nb256  = (n + 255) / 256;
    int eb256  = (e + 255) / 256;
    int nScanB = (n + 1023) / 1024;

    zero_deg<<<nb256, 256>>>(n);
    count_deg<<<eb256, 256>>>(dst, e);
    scan_blocks<<<nScanB, 1024>>>(n);
    scan_bsums<<<1, 1024>>>(nScanB);
    scan_add<<<nb256, 256>>>(n);
    fill_elist<<<eb256, 256>>>(src, dst, e);

    int gblocks = (n + 7) / 8;                    // one warp per node
    gather_h<<<gblocks, 256>>>(reinterpret_cast<const float2*>(feat), n);

    static int smem_set = 0;
    int smemBytes = SMEM_F4_TOTAL * sizeof(float4);   // ~66 KB
    if (!smem_set) {
        cudaFuncSetAttribute(sage_gemm, cudaFuncAttributeMaxDynamicSharedMemorySize,
                             smemBytes);
        smem_set = 1;
    }
    int gemmBlocks = (n + NT_BLOCK - 1) / NT_BLOCK;
    sage_gemm<<<gemmBlocks, 256, smemBytes>>>(
        reinterpret_cast<const float4*>(feat), W_self, W_neigh, bias, out, n);
}

// round 14
// speedup vs baseline: 1.4130x; 1.3063x over previous
#include <cuda_runtime.h>
#include <cuda_bf16.h>
#include <cstdint>

#define MAX_NODES 100000
#define MAX_EDGES 1600000
#define D 64
#define D2 (D / 2)

// ---------------------------------------------------------------------------
// Scratch (allocation-free rule -> device globals).
// ---------------------------------------------------------------------------
__device__ int g_deg[MAX_NODES];
__device__ int g_off[MAX_NODES];
__device__ int g_cursor[MAX_NODES];
__device__ int g_bsum[1024];
__device__ int g_elist[MAX_EDGES];
__device__ float2 g_h2[(size_t)MAX_NODES * D2];   // normalized neighbor means

// ---------------------------------------------------------------------------
// K1: zero degree counters
// ---------------------------------------------------------------------------
__global__ void zero_deg(int n) {
    int i = blockIdx.x * blockDim.x + threadIdx.x;
    if (i < n) g_deg[i] = 0;
}

// ---------------------------------------------------------------------------
// K2: count in-degree per dst (int32 indices)
// ---------------------------------------------------------------------------
__global__ void count_deg(const int* __restrict__ dst, int e) {
    int i = blockIdx.x * blockDim.x + threadIdx.x;
    if (i < e) atomicAdd(&g_deg[dst[i]], 1);
}

// ---------------------------------------------------------------------------
// K3a: per-1024-block exclusive scan; block totals -> g_bsum
// ---------------------------------------------------------------------------
__global__ __launch_bounds__(1024) void scan_blocks(int n) {
    __shared__ int s[1024];
    int tid = threadIdx.x;
    int i = blockIdx.x * 1024 + tid;
    int v = (i < n) ? g_deg[i] : 0;
    s[tid] = v;
    __syncthreads();
#pragma unroll
    for (int ofs = 1; ofs < 1024; ofs <<= 1) {
        int t = (tid >= ofs) ? s[tid - ofs] : 0;
        __syncthreads();
        s[tid] += t;
        __syncthreads();
    }
    if (i < n) g_off[i] = s[tid] - v;            // exclusive within block
    if (tid == 1023) g_bsum[blockIdx.x] = s[1023];
}

// ---------------------------------------------------------------------------
// K3b: add block-prefix (inline reduction — no separate scan_bsums kernel)
// ---------------------------------------------------------------------------
__global__ __launch_bounds__(256) void scan_add(int n) {
    __shared__ int red[256];
    int t = threadIdx.x;
    int group = blockIdx.x >> 2;                  // # of bsums before us (<= 98)
    red[t] = (t < group) ? g_bsum[t] : 0;
    __syncthreads();
#pragma unroll
    for (int ofs = 128; ofs > 0; ofs >>= 1) {
        if (t < ofs) red[t] += red[t + ofs];
        __syncthreads();
    }
    int prefix = red[0];
    int i = blockIdx.x * 256 + t;
    if (i < n) {
        int o = g_off[i] + prefix;
        g_off[i] = o;
        g_cursor[i] = o;
    }
}

// ---------------------------------------------------------------------------
// K4: fill per-dst edge lists (src ids, grouped by dst)
// ---------------------------------------------------------------------------
__global__ void fill_elist(const int* __restrict__ src,
                           const int* __restrict__ dst, int e) {
    int i = blockIdx.x * blockDim.x + threadIdx.x;
    if (i < e) {
        int d = dst[i];
        int pos = atomicAdd(&g_cursor[d], 1);
        g_elist[pos] = src[i];
    }
}

// ---------------------------------------------------------------------------
// K5: gather (fp32). One warp per node; lane = float2 chunk.
// ---------------------------------------------------------------------------
__global__ __launch_bounds__(256)
void gather_h(const float2* __restrict__ feat2, int n) {
    int warp = (blockIdx.x * 256 + threadIdx.x) >> 5;
    int lane = threadIdx.x & 31;
    if (warp >= n) return;
    int node  = warp;
    int start = g_off[node];
    int g     = g_deg[node];

    float2 acc = make_float2(0.f, 0.f);
    int k = 0;
    for (; k + 4 <= g; k += 4) {
        int s0 = g_elist[start + k + 0];
        int s1 = g_elist[start + k + 1];
        int s2 = g_elist[start + k + 2];
        int s3 = g_elist[start + k + 3];
        float2 v0 = feat2[(size_t)s0 * D2 + lane];
        float2 v1 = feat2[(size_t)s1 * D2 + lane];
        float2 v2 = feat2[(size_t)s2 * D2 + lane];
        float2 v3 = feat2[(size_t)s3 * D2 + lane];
        acc.x += v0.x + v1.x + v2.x + v3.x;
        acc.y += v0.y + v1.y + v2.y + v3.y;
    }
    for (; k < g; k++) {
        int s0 = g_elist[start + k];
        float2 v0 = feat2[(size_t)s0 * D2 + lane];
        acc.x += v0.x; acc.y += v0.y;
    }
    float inv = 1.0f / (float)max(g, 1);
    acc.x *= inv; acc.y *= inv;
    g_h2[(size_t)node * D2 + lane] = acc;
}

// ---------------------------------------------------------------------------
// K6: tf32 mma.sync dual GEMM + bias + ReLU (legacy tensor path — compiles
// for plain sm_103 target, unlike tcgen05).
// CTA = 128 threads (4 warps) = 128 nodes; warp w owns rows 32w..32w+31,
// all 64 output cols. D = F @ Ws^T' + H @ Wn^T' accumulated in the SAME
// C fragments. Stride-68 smem rows -> conflict-free fragment loads.
// All operands tf32-rounded (cvt.rna) once at staging.
// ---------------------------------------------------------------------------
#define SROWF 68                        // smem row stride in floats

#define OFF_WS   0                              // Wt_self [64][68] f32
#define OFF_WN   (OFF_WS + 64 * SROWF * 4)      // Wt_neigh
#define OFF_AF   (OFF_WN + 64 * SROWF * 4)      // feat tile [128][68]
#define OFF_AH   (OFF_AF + 128 * SROWF * 4)     // h tile
#define OFF_BIAS (OFF_AH + 128 * SROWF * 4)     // bias [64]
#define SMEM_GEMM_BYTES (OFF_BIAS + 256)

__device__ __forceinline__ uint32_t tf32r(float x) {
    uint32_t r;
    asm("cvt.rna.tf32.f32 %0, %1;" : "=r"(r) : "f"(x));
    return r;
}

__device__ __forceinline__ void mma_tf32(float c[4], const uint32_t a[4],
                                         const uint32_t b[2]) {
    asm volatile(
        "mma.sync.aligned.m16n8k8.row.col.f32.tf32.tf32.f32 "
        "{%0,%1,%2,%3}, {%4,%5,%6,%7}, {%8,%9}, {%0,%1,%2,%3};"
        : "+f"(c[0]), "+f"(c[1]), "+f"(c[2]), "+f"(c[3])
        : "r"(a[0]), "r"(a[1]), "r"(a[2]), "r"(a[3]), "r"(b[0]), "r"(b[1]));
}

__global__ __launch_bounds__(128)
void sage_gemm(const float4* __restrict__ feat4,
               const float* __restrict__ W_self,
               const float* __restrict__ W_neigh,
               const float* __restrict__ bias,
               float* __restrict__ out,
               int n) {
    extern __shared__ __align__(16) char smem[];
    float* sWS = reinterpret_cast<float*>(smem + OFF_WS);   // [j][k], stride 68
    float* sWN = reinterpret_cast<float*>(smem + OFF_WN);
    float* sAF = reinterpret_cast<float*>(smem + OFF_AF);   // [row][k], stride 68
    float* sAH = reinterpret_cast<float*>(smem + OFF_AH);
    float* sB  = reinterpret_cast<float*>(smem + OFF_BIAS);

    int tid  = threadIdx.x;
    int base = blockIdx.x * 128;

    // ---- stage weights transposed (Wt[j][k] = W[k][j]), tf32-rounded ----
#pragma unroll
    for (int q = 0; q < 32; q++) {
        int i = tid + 128 * q;          // 4096 = 64k x 64j
        int k = i >> 6, j = i & 63;
        sWS[j * SROWF + k] = __uint_as_float(tf32r(W_self[i]));
        sWN[j * SROWF + k] = __uint_as_float(tf32r(W_neigh[i]));
    }

    // ---- stage feat / h tiles (128 rows), tf32-rounded ----
    {
        const float4* h4 = reinterpret_cast<const float4*>(g_h2);
        float4 fz = make_float4(0.f, 0.f, 0.f, 0.f);
#pragma unroll
        for (int q = 0; q < 16; q++) {
            int idx = tid + 128 * q;    // 2048 = 128 rows x 16 float4
            int row = idx >> 4, c4 = idx & 15;
            int gn  = base + row;
            float4 fv = fz, hv = fz;
            if (gn < n) {
                fv = feat4[(size_t)gn * 16 + c4];
                hv = h4[(size_t)gn * 16 + c4];
            }
            float4 ft, ht;
            ft.x = __uint_as_float(tf32r(fv.x)); ft.y = __uint_as_float(tf32r(fv.y));
            ft.z = __uint_as_float(tf32r(fv.z)); ft.w = __uint_as_float(tf32r(fv.w));
            ht.x = __uint_as_float(tf32r(hv.x)); ht.y = __uint_as_float(tf32r(hv.y));
            ht.z = __uint_as_float(tf32r(hv.z)); ht.w = __uint_as_float(tf32r(hv.w));
            *reinterpret_cast<float4*>(&sAF[row * SROWF + c4 * 4]) = ft;
            *reinterpret_cast<float4*>(&sAH[row * SROWF + c4 * 4]) = ht;
        }
    }
    if (tid < 64) sB[tid] = bias[tid];
    __syncthreads();

    // ---- per-warp MMA: rows m0..m0+31, cols 0..63 ----
    int wid = tid >> 5;
    int lane = tid & 31;
    int qr = lane >> 2;                 // group id 0..7
    int qc = lane & 3;                  // thread-in-group 0..3
    int m0 = wid * 32;

    float c[2][8][4];
#pragma unroll
    for (int mt = 0; mt < 2; mt++)
#pragma unroll
        for (int nb = 0; nb < 8; nb++)
#pragma unroll
            for (int x = 0; x < 4; x++) c[mt][nb][x] = 0.f;

#pragma unroll
    for (int k8 = 0; k8 < 8; k8++) {
        int kb = k8 * 8;

        // B fragments for all 8 n-tiles at this k-step (self + neigh)
        uint32_t bs[8][2], bn[8][2];
#pragma unroll
        for (int nb = 0; nb < 8; nb++) {
            int nrow = nb * 8 + qr;
            bs[nb][0] = __float_as_uint(sWS[nrow * SROWF + kb + qc]);
            bs[nb][1] = __float_as_uint(sWS[nrow * SROWF + kb + qc + 4]);
            bn[nb][0] = __float_as_uint(sWN[nrow * SROWF + kb + qc]);
            bn[nb][1] = __float_as_uint(sWN[nrow * SROWF + kb + qc + 4]);
        }

#pragma unroll
        for (int mt = 0; mt < 2; mt++) {
            int mr = m0 + mt * 16 + qr;
            uint32_t af[4], ah[4];
            af[0] = __float_as_uint(sAF[mr * SROWF + kb + qc]);
            af[1] = __float_as_uint(sAF[(mr + 8) * SROWF + kb + qc]);
            af[2] = __float_as_uint(sAF[mr * SROWF + kb + qc + 4]);
            af[3] = __float_as_uint(sAF[(mr + 8) * SROWF + kb + qc + 4]);
            ah[0] = __float_as_uint(sAH[mr * SROWF + kb + qc]);
            ah[1] = __float_as_uint(sAH[(mr + 8) * SROWF + kb + qc]);
            ah[2] = __float_as_uint(sAH[mr * SROWF + kb + qc + 4]);
            ah[3] = __float_as_uint(sAH[(mr + 8) * SROWF + kb + qc + 4]);
#pragma unroll
            for (int nb = 0; nb < 8; nb++) {
                mma_tf32(c[mt][nb], af, bs[nb]);
                mma_tf32(c[mt][nb], ah, bn[nb]);
            }
        }
    }

    // ---- epilogue: bias + ReLU + store (float2 per c-pair) ----
#pragma unroll
    for (int mt = 0; mt < 2; mt++) {
#pragma unroll
        for (int nb = 0; nb < 8; nb++) {
            int col = nb * 8 + 2 * qc;
            float b0 = sB[col], b1 = sB[col + 1];
            int r0 = base + m0 + mt * 16 + qr;
            int r1 = r0 + 8;
            if (r0 < n) {
                float2 v;
                v.x = fmaxf(c[mt][nb][0] + b0, 0.f);
                v.y = fmaxf(c[mt][nb][1] + b1, 0.f);
                *reinterpret_cast<float2*>(out + (size_t)r0 * D + col) = v;
            }
            if (r1 < n) {
                float2 v;
                v.x = fmaxf(c[mt][nb][2] + b0, 0.f);
                v.y = fmaxf(c[mt][nb][3] + b1, 0.f);
                *reinterpret_cast<float2*>(out + (size_t)r1 * D + col) = v;
            }
        }
    }
}

// ---------------------------------------------------------------------------
// Launch.  Inputs: feat[N*64] f32, src[E] i32, dst[E] i32,
//                  W_self[64*64] f32, W_neigh[64*64] f32, bias[64] f32
// ---------------------------------------------------------------------------
extern "C" void kernel_launch(void* const* d_in, const int* in_sizes, int n_in,
                              void* d_out, int out_size) {
    const float* feat    = (const float*)d_in[0];
    const int*   src     = (const int*)d_in[1];
    const int*   dst     = (const int*)d_in[2];
    const float* W_self  = (const float*)d_in[3];
    const float* W_neigh = (const float*)d_in[4];
    const float* bias    = (const float*)d_in[5];
    float*       out     = (float*)d_out;

    int n = in_sizes[0] / D;
    int e = in_sizes[1];

    int nb256  = (n + 255) / 256;
    int eb256  = (e + 255) / 256;
    int nScanB = (n + 1023) / 1024;

    zero_deg<<<nb256, 256>>>(n);
    count_deg<<<eb256, 256>>>(dst, e);
    scan_blocks<<<nScanB, 1024>>>(n);
    scan_add<<<nb256, 256>>>(n);
    fill_elist<<<eb256, 256>>>(src, dst, e);

    int gblocks = (n + 7) / 8;                    // one warp per node
    gather_h<<<gblocks, 256>>>(reinterpret_cast<const float2*>(feat), n);

    static int smem_set = 0;
    if (!smem_set) {
        cudaFuncSetAttribute(sage_gemm, cudaFuncAttributeMaxDynamicSharedMemorySize,
                             SMEM_GEMM_BYTES);
        smem_set = 1;
    }
    int gemmBlocks = (n + 127) / 128;
    sage_gemm<<<gemmBlocks, 128, SMEM_GEMM_BYTES>>>(
        reinterpret_cast<const float4*>(feat), W_self, W_neigh, bias, out, n);
}